// round 13
// baseline (speedup 1.0000x reference)
#include <cuda_runtime.h>
#include <cuda_fp16.h>
#include <mma.h>
#include <math.h>

using namespace nvcuda;

#define H_DIM   4096
#define BATCH   64
#define T_STEPS 128
#define I_DIM   1024
#define NNZ_IH  131072
#define NNZ_HH  262144

#define ROWS_PER_BLK 8

// ---------------- scratch (device globals; no runtime allocation) ----------------
__device__ __half g_x16[(size_t)T_STEPS * I_DIM * BATCH];        // x as (T, I, B) fp16
__device__ __half g_pre[(size_t)T_STEPS * H_DIM * BATCH];        // W_ih x_t, fp16
__device__ __half g_hall[(size_t)(T_STEPS + 1) * H_DIM * BATCH]; // h(0..T), (H,B) fp16
__device__ float  g_W32[(size_t)H_DIM * I_DIM];                  // dense W_ih fp32 accum
__device__ __half g_W16[(size_t)H_DIM * I_DIM];                  // dense W_ih fp16
__device__ int    g_hh_ptr[H_DIM + 1];
__device__ unsigned g_hh_pkc[NNZ_HH];  // packed: low16 = col, high16 = fp16 val bits
__device__ int    g_cnt[H_DIM];

// ---------------- cp.async helpers ----------------
__device__ __forceinline__ void cpa16(void* dst, const void* src) {
    unsigned d = (unsigned)__cvta_generic_to_shared(dst);
    asm volatile("cp.async.cg.shared.global [%0], [%1], 16;\n" :: "r"(d), "l"(src));
}
#define CPA_COMMIT() asm volatile("cp.async.commit_group;\n" ::)
#define CPA_WAIT(n)  asm volatile("cp.async.wait_group %0;\n" :: "n"(n))

// ---------------- setup kernel 1: zero everything ----------------
__global__ void k_init() {
    int idx = blockIdx.x * blockDim.x + threadIdx.x;
    if (idx < H_DIM * I_DIM / 4)
        ((float4*)g_W32)[idx] = make_float4(0.f, 0.f, 0.f, 0.f);
    if (idx < H_DIM * BATCH / 2)
        ((__half2*)g_hall)[idx] = __floats2half2_rn(0.f, 0.f);   // h(0) = 0
    if (idx < H_DIM) g_cnt[idx] = 0;
}

// ---------------- setup kernel 2: hh row histogram ----------------
__global__ void k_hist(const int* __restrict__ hh_rows) {
    int k = blockIdx.x * blockDim.x + threadIdx.x;
    if (k < NNZ_HH) atomicAdd(&g_cnt[hh_rows[k]], 1);
}

// ---------------- setup kernel 3: exclusive scan + cnt reset ----------------
__global__ void k_scan() {
    __shared__ int sums[1024];
    int tid  = threadIdx.x;
    int base = tid * 4;
    int v0 = g_cnt[base + 0];
    int v1 = g_cnt[base + 1];
    int v2 = g_cnt[base + 2];
    int v3 = g_cnt[base + 3];
    int local = v0 + v1 + v2 + v3;
    sums[tid] = local;
    __syncthreads();
    for (int off = 1; off < 1024; off <<= 1) {
        int t = (tid >= off) ? sums[tid - off] : 0;
        __syncthreads();
        sums[tid] += t;
        __syncthreads();
    }
    int excl = sums[tid] - local;
    g_hh_ptr[base + 0] = excl;
    g_hh_ptr[base + 1] = excl + v0;
    g_hh_ptr[base + 2] = excl + v0 + v1;
    g_hh_ptr[base + 3] = excl + v0 + v1 + v2;
    if (tid == 1023) g_hh_ptr[H_DIM] = sums[1023];
    g_cnt[base + 0] = 0;
    g_cnt[base + 1] = 0;
    g_cnt[base + 2] = 0;
    g_cnt[base + 3] = 0;
}

// ---------------- setup kernel 4: hh scatter + ih densify ----------------
__global__ void k_build(const int* __restrict__ ih_rows, const int* __restrict__ ih_cols,
                        const float* __restrict__ ih_vals,
                        const int* __restrict__ hh_rows, const int* __restrict__ hh_cols,
                        const float* __restrict__ hh_vals) {
    int k = blockIdx.x * blockDim.x + threadIdx.x;
    if (k < NNZ_IH)
        atomicAdd(&g_W32[(size_t)ih_rows[k] * I_DIM + ih_cols[k]], ih_vals[k]);
    if (k < NNZ_HH) {
        int r = hh_rows[k];
        int p = g_hh_ptr[r] + atomicAdd(&g_cnt[r], 1);
        unsigned hv = (unsigned)__half_as_ushort(__float2half(hh_vals[k]));
        g_hh_pkc[p] = (unsigned)hh_cols[k] | (hv << 16);
    }
}

// ---------------- setup kernel 5: x transpose (z<128) + W cvt (z>=128) ----------------
__global__ void k_prep(const float* __restrict__ x) {
    int z = blockIdx.z;
    if (z < T_STEPS) {
        __shared__ float tile[32][33];
        int t  = z;
        int i0 = blockIdx.x * 32;
        int b0 = blockIdx.y * 32;
        int b = b0 + threadIdx.y;
        int i = i0 + threadIdx.x;
        tile[threadIdx.y][threadIdx.x] = x[((size_t)b * T_STEPS + t) * I_DIM + i];
        __syncthreads();
        int iw = i0 + threadIdx.y;
        int bw = b0 + threadIdx.x;
        g_x16[((size_t)t * I_DIM + iw) * BATCH + bw] =
            __float2half(tile[threadIdx.x][threadIdx.y]);
    } else if (blockIdx.x == 0 && blockIdx.y == 0) {
        int slab = z - T_STEPS;
        int tid32 = threadIdx.y * 32 + threadIdx.x;
        #pragma unroll
        for (int j = 0; j < 16; j++) {
            size_t idx = (size_t)slab * 16384 + (size_t)j * 1024 + tid32;
            float2 v = ((const float2*)g_W32)[idx];
            ((__half2*)g_W16)[idx] = __floats2half2_rn(v.x, v.y);
        }
    }
}

// ---------------- pre GEMM: cp.async double-buffered wmma ----------------
#define A_LD 72
#define B_LD 136
#define A_BYTES (128 * A_LD * 2)   // 18432
#define B_BYTES (64 * B_LD * 2)    // 17408
#define GEMM_SMEM (2 * (A_BYTES + B_BYTES))   // 71680

__global__ void __launch_bounds__(256)
k_gemm_pre() {
    extern __shared__ char smbase[];
    __half* Asm[2] = { (__half*)smbase, (__half*)(smbase + A_BYTES) };
    __half* Bsm[2] = { (__half*)(smbase + 2 * A_BYTES),
                       (__half*)(smbase + 2 * A_BYTES + B_BYTES) };
    float* fbuf = (float*)smbase;

    int tid  = threadIdx.x;
    int w    = tid >> 5;
    int lane = tid & 31;
    int wm   = w >> 1;
    int wn   = w & 1;
    int row0 = blockIdx.x * 128;
    int t0   = blockIdx.y * 2;

    const __half* __restrict__ Wp = g_W16 + (size_t)row0 * I_DIM;

    auto load_chunk = [&](int kc, int s) {
        const __half* asrc = Wp + kc * 64;
        #pragma unroll
        for (int p = 0; p < 4; p++) {
            int i   = tid + p * 256;
            int row = i >> 3;
            int seg = i & 7;
            cpa16(&Asm[s][row * A_LD + seg * 8],
                  asrc + (size_t)row * I_DIM + seg * 8);
        }
        #pragma unroll
        for (int p = 0; p < 4; p++) {
            int i    = tid + p * 256;
            int k    = i >> 4;
            int rest = i & 15;
            int tt   = rest >> 3;
            int seg  = rest & 7;
            cpa16(&Bsm[s][k * B_LD + tt * 64 + seg * 8],
                  g_x16 + (size_t)(t0 + tt) * I_DIM * BATCH
                        + (size_t)(kc * 64 + k) * BATCH + seg * 8);
        }
    };

    wmma::fragment<wmma::accumulator, 16, 16, 16, float> c[2][4];
    #pragma unroll
    for (int i = 0; i < 2; i++)
        #pragma unroll
        for (int j = 0; j < 4; j++)
            wmma::fill_fragment(c[i][j], 0.0f);

    load_chunk(0, 0);
    CPA_COMMIT();

    for (int kc = 0; kc < 16; kc++) {
        int s = kc & 1;
        if (kc < 15) {
            load_chunk(kc + 1, s ^ 1);
            CPA_COMMIT();
            CPA_WAIT(1);
        } else {
            CPA_WAIT(0);
        }
        __syncthreads();

        #pragma unroll
        for (int kk = 0; kk < 4; kk++) {
            wmma::fragment<wmma::matrix_a, 16, 16, 16, __half, wmma::row_major> a[2];
            wmma::fragment<wmma::matrix_b, 16, 16, 16, __half, wmma::row_major> b[4];
            wmma::load_matrix_sync(a[0], &Asm[s][(wm * 32) * A_LD + kk * 16], A_LD);
            wmma::load_matrix_sync(a[1], &Asm[s][(wm * 32 + 16) * A_LD + kk * 16], A_LD);
            #pragma unroll
            for (int j = 0; j < 4; j++)
                wmma::load_matrix_sync(b[j], &Bsm[s][(kk * 16) * B_LD + wn * 64 + j * 16], B_LD);
            #pragma unroll
            for (int i = 0; i < 2; i++)
                #pragma unroll
                for (int j = 0; j < 4; j++)
                    wmma::mma_sync(c[i][j], a[i], b[j], c[i][j]);
        }
        __syncthreads();
    }

    float* buf = fbuf + w * 2048;
    #pragma unroll
    for (int i = 0; i < 2; i++)
        #pragma unroll
        for (int j = 0; j < 4; j++)
            wmma::store_matrix_sync(buf + i * 16 * 64 + j * 16, c[i][j], 64,
                                    wmma::mem_row_major);
    __syncwarp();

    __half2* dst = (__half2*)(g_pre + (size_t)(t0 + wn) * H_DIM * BATCH);
    #pragma unroll
    for (int rr = 0; rr < 32; rr++) {
        float2 v = ((const float2*)(buf + rr * 64))[lane];
        dst[(size_t)(row0 + wm * 32 + rr) * (BATCH / 2) + lane] =
            __floats2half2_rn(v.x, v.y);
    }
}

// ---------------- per-timestep kernel (hh only; no out traffic) ----------------
// block (32,16): each row served by a warp PAIR (k-split). Reads h_all[t],
// writes h_all[t+1] (which doubles as the output record). One syncthreads.
__global__ void __launch_bounds__(512)
k_step(const float* __restrict__ bias, int t) {
    int lane = threadIdx.x;
    int ty   = threadIdx.y;            // 0..15
    int ry   = ty & 7;
    int half = ty >> 3;
    int r    = blockIdx.x * ROWS_PER_BLK + ry;

    const __half2* __restrict__ hb =
        (const __half2*)(g_hall + (size_t)t * H_DIM * BATCH);

    int k0 = g_hh_ptr[r];
    int k1 = g_hh_ptr[r + 1];
    int mid = (k0 + k1 + 1) >> 1;
    int ka = half ? mid : k0;
    int kb = half ? k1  : mid;

    float ax = 0.0f, ay = 0.0f;
    #pragma unroll 4
    for (int k = ka; k < kb; k++) {
        unsigned w = g_hh_pkc[k];
        float v = __half2float(__ushort_as_half((unsigned short)(w >> 16)));
        float2 f = __half22float2(hb[(w & 0xFFFFu) * (BATCH / 2) + lane]);
        ax += v * f.x;
        ay += v * f.y;
    }

    __shared__ float2 part[ROWS_PER_BLK][32];
    if (half == 1) part[ry][lane] = make_float2(ax, ay);
    __syncthreads();

    if (half == 0) {
        float2 p = part[ry][lane];
        float bv = bias[r];
        float2 pre = __half22float2(
            ((const __half2*)(g_pre + (size_t)t * H_DIM * BATCH))
                [r * (BATCH / 2) + lane]);
        float hx = tanhf(bv + pre.x + ax + p.x);
        float hy = tanhf(bv + pre.y + ay + p.y);

        ((__half2*)(g_hall + (size_t)(t + 1) * H_DIM * BATCH))
            [r * (BATCH / 2) + lane] = __floats2half2_rn(hx, hy);
    }
}

// ---------------- final: h_all (T+1,H,B) fp16 -> out (B,T,H) fp32 ----------------
// tiled transpose; fully parallel, runs once.
__global__ void __launch_bounds__(1024)
k_out(float* __restrict__ out) {
    __shared__ __half tile[32][33];
    int t  = blockIdx.z;
    int r0 = blockIdx.x * 32;
    int b0 = blockIdx.y * 32;

    // read h_all[t+1][r0+ty][b0+tx] (coalesced along b)
    tile[threadIdx.y][threadIdx.x] =
        g_hall[((size_t)(t + 1) * H_DIM + (r0 + threadIdx.y)) * BATCH
               + b0 + threadIdx.x];
    __syncthreads();
    // write out[b0+ty][t][r0+tx] (coalesced along r)
    out[(((size_t)(b0 + threadIdx.y)) * T_STEPS + t) * H_DIM + r0 + threadIdx.x] =
        __half2float(tile[threadIdx.x][threadIdx.y]);
}

// ---------------- launch ----------------
extern "C" void kernel_launch(void* const* d_in, const int* in_sizes, int n_in,
                              void* d_out, int out_size) {
    const float* x       = (const float*)d_in[0];
    const float* ih_vals = (const float*)d_in[1];
    const float* hh_vals = (const float*)d_in[2];
    const float* hh_bias = (const float*)d_in[3];
    const int*   ih_rows = (const int*)  d_in[4];
    const int*   ih_cols = (const int*)  d_in[5];
    const int*   hh_rows = (const int*)  d_in[6];
    const int*   hh_cols = (const int*)  d_in[7];
    float* out = (float*)d_out;

    static int smem_set = 0;
    if (!smem_set) {
        cudaFuncSetAttribute(k_gemm_pre, cudaFuncAttributeMaxDynamicSharedMemorySize,
                             GEMM_SMEM);
        smem_set = 1;
    }

    // ---- setup (5 launches) ----
    k_init<<<H_DIM * I_DIM / 4 / 256, 256>>>();
    k_hist<<<NNZ_HH / 256, 256>>>(hh_rows);
    k_scan<<<1, 1024>>>();
    k_build<<<NNZ_HH / 256, 256>>>(ih_rows, ih_cols, ih_vals,
                                   hh_rows, hh_cols, hh_vals);
    k_prep<<<dim3(32, 2, 256), dim3(32, 32)>>>(x);

    // ---- ih term for all t via tensor cores ----
    k_gemm_pre<<<dim3(H_DIM / 128, T_STEPS / 2), 256, GEMM_SMEM>>>();

    // ---- sequential recurrence (hh only, no out traffic) ----
    for (int t = 0; t < T_STEPS; t++) {
        k_step<<<H_DIM / ROWS_PER_BLK, dim3(32, 16)>>>(hh_bias, t);
    }

    // ---- emit out once, fully parallel ----
    k_out<<<dim3(H_DIM / 32, BATCH / 32, T_STEPS), dim3(32, 32)>>>(out);
}

// round 14
// speedup vs baseline: 1.0271x; 1.0271x over previous
#include <cuda_runtime.h>
#include <cuda_fp16.h>
#include <math.h>

#define H_DIM   4096
#define BATCH   64
#define T_STEPS 128
#define I_DIM   1024
#define NNZ_IH  131072
#define NNZ_HH  262144

#define ROWS_PER_BLK 8

// ---------------- scratch (device globals; no runtime allocation) ----------------
__device__ __half g_x16[(size_t)T_STEPS * I_DIM * BATCH];   // x as (T, I, B) fp16
__device__ __half g_pre[(size_t)T_STEPS * H_DIM * BATCH];   // bias + W_ih x_t, fp16
__device__ __half g_h16[2][H_DIM * BATCH];                  // h ping-pong (H, B) fp16
__device__ int    g_ih_ptr[H_DIM + 1];
__device__ int    g_hh_ptr[H_DIM + 1];
__device__ unsigned g_ih_pkc[NNZ_IH];  // packed: low16 = col, high16 = fp16 val bits
__device__ unsigned g_hh_pkc[NNZ_HH];
__device__ int    g_cnt[2 * H_DIM];

// ---------------- setup kernels (R7-proven) ----------------
__global__ void k_zero_all() {
    int idx = blockIdx.x * blockDim.x + threadIdx.x;
    if (idx < H_DIM * BATCH) g_h16[0][idx] = __float2half(0.0f);
    if (idx < 2 * H_DIM)     g_cnt[idx]   = 0;
}

__global__ void k_zero_cnt() {
    int idx = blockIdx.x * blockDim.x + threadIdx.x;
    if (idx < 2 * H_DIM) g_cnt[idx] = 0;
}

__global__ void k_hist(const int* __restrict__ ih_rows, const int* __restrict__ hh_rows) {
    int k = blockIdx.x * blockDim.x + threadIdx.x;
    if (k < NNZ_IH) atomicAdd(&g_cnt[ih_rows[k]], 1);
    if (k < NNZ_HH) atomicAdd(&g_cnt[H_DIM + hh_rows[k]], 1);
}

// exclusive scan of 4096 counts -> row pointers (one block per matrix)
__global__ void k_scan() {
    __shared__ int sums[1024];
    int which = blockIdx.x;              // 0 = ih, 1 = hh
    int* cnt = &g_cnt[which * H_DIM];
    int* ptr = which ? g_hh_ptr : g_ih_ptr;
    int tid  = threadIdx.x;
    int base = tid * 4;
    int v0 = cnt[base + 0];
    int v1 = cnt[base + 1];
    int v2 = cnt[base + 2];
    int v3 = cnt[base + 3];
    int local = v0 + v1 + v2 + v3;
    sums[tid] = local;
    __syncthreads();
    for (int off = 1; off < 1024; off <<= 1) {
        int t = (tid >= off) ? sums[tid - off] : 0;
        __syncthreads();
        sums[tid] += t;
        __syncthreads();
    }
    int excl = sums[tid] - local;
    ptr[base + 0] = excl;
    ptr[base + 1] = excl + v0;
    ptr[base + 2] = excl + v0 + v1;
    ptr[base + 3] = excl + v0 + v1 + v2;
    if (tid == 1023) ptr[H_DIM] = sums[1023];
}

__global__ void k_scatter(const int* __restrict__ ih_rows, const int* __restrict__ ih_cols,
                          const float* __restrict__ ih_vals,
                          const int* __restrict__ hh_rows, const int* __restrict__ hh_cols,
                          const float* __restrict__ hh_vals) {
    int k = blockIdx.x * blockDim.x + threadIdx.x;
    if (k < NNZ_IH) {
        int r = ih_rows[k];
        int p = g_ih_ptr[r] + atomicAdd(&g_cnt[r], 1);
        unsigned hv = (unsigned)__half_as_ushort(__float2half(ih_vals[k]));
        g_ih_pkc[p] = (unsigned)ih_cols[k] | (hv << 16);
    }
    if (k < NNZ_HH) {
        int r = hh_rows[k];
        int p = g_hh_ptr[r] + atomicAdd(&g_cnt[H_DIM + r], 1);
        unsigned hv = (unsigned)__half_as_ushort(__float2half(hh_vals[k]));
        g_hh_pkc[p] = (unsigned)hh_cols[k] | (hv << 16);
    }
}

// x (B,T,I) fp32 -> g_x16 (T,I,B) fp16
__global__ void k_transpose_x(const float* __restrict__ x) {
    __shared__ float tile[32][33];
    int t  = blockIdx.z;
    int i0 = blockIdx.x * 32;
    int b0 = blockIdx.y * 32;
    int b = b0 + threadIdx.y;
    int i = i0 + threadIdx.x;
    tile[threadIdx.y][threadIdx.x] = x[((size_t)b * T_STEPS + t) * I_DIM + i];
    __syncthreads();
    int iw = i0 + threadIdx.y;
    int bw = b0 + threadIdx.x;
    g_x16[((size_t)t * I_DIM + iw) * BATCH + bw] =
        __float2half(tile[threadIdx.x][threadIdx.y]);
}

// ---------------- ih precompute: pre[t] = bias + W_ih x_t, all t in parallel ----------------
// grid (512 rowblocks, 128 t), block (32, 8): warp = one (row, t); fully parallel,
// no recurrence -> runs at the LTS cap.
__global__ void __launch_bounds__(256)
k_preih(const float* __restrict__ bias) {
    int lane = threadIdx.x;
    int ty   = threadIdx.y;
    int r    = blockIdx.x * ROWS_PER_BLK + ty;
    int t    = blockIdx.y;

    const __half2* __restrict__ xb =
        (const __half2*)(g_x16 + (size_t)t * I_DIM * BATCH);

    float bv = bias[r];
    float ax = bv, ay = bv;

    int k0 = g_ih_ptr[r];
    int k1 = g_ih_ptr[r + 1];
    #pragma unroll 4
    for (int k = k0; k < k1; k++) {
        unsigned w = g_ih_pkc[k];
        float v = __half2float(__ushort_as_half((unsigned short)(w >> 16)));
        float2 f = __half22float2(xb[(w & 0xFFFFu) * (BATCH / 2) + lane]);
        ax += v * f.x;
        ay += v * f.y;
    }

    ((__half2*)(g_pre + (size_t)t * H_DIM * BATCH))[r * (BATCH / 2) + lane] =
        __floats2half2_rn(ax, ay);
}

// ---------------- per-timestep kernel (hh only; R7-proven structure) ----------------
// block (32, 16): row handled by a warp PAIR (half = ty>>3) splitting its entry
// range contiguously -> 8192 warps chip-wide keeps the LTS pipe full.
__global__ void __launch_bounds__(512)
k_step(float* __restrict__ out, int t, int prev) {
    int lane = threadIdx.x;
    int ty   = threadIdx.y;            // 0..15
    int ry   = ty & 7;
    int half = ty >> 3;
    int r    = blockIdx.x * ROWS_PER_BLK + ry;

    const __half2* __restrict__ hb = (const __half2*)g_h16[prev];

    int k0 = g_hh_ptr[r];
    int k1 = g_hh_ptr[r + 1];
    int mid = (k0 + k1 + 1) >> 1;
    int ka = half ? mid : k0;
    int kb = half ? k1  : mid;

    float ax = 0.0f, ay = 0.0f;
    #pragma unroll 4
    for (int k = ka; k < kb; k++) {
        unsigned w = g_hh_pkc[k];
        float v = __half2float(__ushort_as_half((unsigned short)(w >> 16)));
        float2 f = __half22float2(hb[(w & 0xFFFFu) * (BATCH / 2) + lane]);
        ax += v * f.x;
        ay += v * f.y;
    }

    __shared__ float2 part[ROWS_PER_BLK][32];
    __shared__ float  tile[ROWS_PER_BLK][BATCH + 1];

    if (half == 1) part[ry][lane] = make_float2(ax, ay);
    __syncthreads();

    if (half == 0) {
        float2 p = part[ry][lane];
        float2 pre = __half22float2(
            ((const __half2*)(g_pre + (size_t)t * H_DIM * BATCH))
                [r * (BATCH / 2) + lane]);
        float hx = tanhf(pre.x + ax + p.x);
        float hy = tanhf(pre.y + ay + p.y);

        // h(t) fp16: one 128B line per warp
        ((__half2*)g_h16[prev ^ 1])[r * (BATCH / 2) + lane] =
            __floats2half2_rn(hx, hy);

        tile[ry][2 * lane]     = hx;
        tile[ry][2 * lane + 1] = hy;
    }
    __syncthreads();

    // out (B,T,H) fp32, coalesced: 512 threads cover 512 elements
    int idx = ty * 32 + lane;                       // 0..511
    int b   = idx >> 3;                             // 0..63
    int rr  = idx & 7;                              // 0..7
    out[((size_t)b * T_STEPS + t) * H_DIM + blockIdx.x * ROWS_PER_BLK + rr] =
        tile[rr][b];
}

// ---------------- launch ----------------
extern "C" void kernel_launch(void* const* d_in, const int* in_sizes, int n_in,
                              void* d_out, int out_size) {
    const float* x       = (const float*)d_in[0];
    const float* ih_vals = (const float*)d_in[1];
    const float* hh_vals = (const float*)d_in[2];
    const float* hh_bias = (const float*)d_in[3];
    const int*   ih_rows = (const int*)  d_in[4];
    const int*   ih_cols = (const int*)  d_in[5];
    const int*   hh_rows = (const int*)  d_in[6];
    const int*   hh_cols = (const int*)  d_in[7];
    float* out = (float*)d_out;

    // CSR build (packed 4B entries) + x transpose/convert
    k_zero_all<<<(H_DIM * BATCH + 255) / 256, 256>>>();
    k_hist<<<(NNZ_HH + 255) / 256, 256>>>(ih_rows, hh_rows);
    k_scan<<<2, 1024>>>();
    k_zero_cnt<<<(2 * H_DIM + 255) / 256, 256>>>();
    k_scatter<<<(NNZ_HH + 255) / 256, 256>>>(ih_rows, ih_cols, ih_vals,
                                             hh_rows, hh_cols, hh_vals);
    k_transpose_x<<<dim3(I_DIM / 32, BATCH / 32, T_STEPS), dim3(32, 32)>>>(x);

    // ih term for all timesteps at once (no recurrence -> full parallelism)
    k_preih<<<dim3(H_DIM / ROWS_PER_BLK, T_STEPS), dim3(32, ROWS_PER_BLK)>>>(hh_bias);

    // sequential recurrence: hh gathers only
    for (int t = 0; t < T_STEPS; t++) {
        k_step<<<H_DIM / ROWS_PER_BLK, dim3(32, 16)>>>(out, t, t & 1);
    }
}

// round 15
// speedup vs baseline: 1.0907x; 1.0619x over previous
#include <cuda_runtime.h>
#include <cuda_fp16.h>
#include <mma.h>
#include <math.h>

using namespace nvcuda;

#define H_DIM   4096
#define BATCH   64
#define T_STEPS 128
#define I_DIM   1024
#define NNZ_IH  131072
#define NNZ_HH  262144

#define ROWS_PER_BLK 8

// ---------------- scratch (device globals; no runtime allocation) ----------------
__device__ __half g_x16[(size_t)T_STEPS * I_DIM * BATCH];   // x as (T, I, B) fp16
__device__ __half g_pre[(size_t)T_STEPS * H_DIM * BATCH];   // W_ih x_t (no bias), fp16
__device__ __half g_h16[2][H_DIM * BATCH];                  // h ping-pong (H, B) fp16
__device__ float  g_W32[(size_t)H_DIM * I_DIM];             // dense W_ih fp32 accum
__device__ __half g_W16[(size_t)H_DIM * I_DIM];             // dense W_ih fp16
__device__ int    g_hh_ptr[H_DIM + 1];
__device__ int2   g_hh_pk[NNZ_HH];     // (col, val fp32 bits) — R7/R10-proven format
__device__ int    g_cnt[H_DIM];

// ---------------- cp.async helpers ----------------
__device__ __forceinline__ void cpa16(void* dst, const void* src) {
    unsigned d = (unsigned)__cvta_generic_to_shared(dst);
    asm volatile("cp.async.cg.shared.global [%0], [%1], 16;\n" :: "r"(d), "l"(src));
}
#define CPA_COMMIT() asm volatile("cp.async.commit_group;\n" ::)
#define CPA_WAIT(n)  asm volatile("cp.async.wait_group %0;\n" :: "n"(n))

// ---------------- setup: zero W32 + h(0) + cnt (R12-proven) ----------------
__global__ void k_init() {
    int idx = blockIdx.x * blockDim.x + threadIdx.x;
    if (idx < H_DIM * I_DIM / 4)
        ((float4*)g_W32)[idx] = make_float4(0.f, 0.f, 0.f, 0.f);
    if (idx < H_DIM * BATCH / 2)
        ((__half2*)g_h16[0])[idx] = __floats2half2_rn(0.f, 0.f);
    if (idx < H_DIM) g_cnt[idx] = 0;
}

// ---------------- hh row histogram ----------------
__global__ void k_hist(const int* __restrict__ hh_rows) {
    int k = blockIdx.x * blockDim.x + threadIdx.x;
    if (k < NNZ_HH) atomicAdd(&g_cnt[hh_rows[k]], 1);
}

// ---------------- exclusive scan of 4096 counts + cnt reset (R12-proven) ----------------
__global__ void k_scan() {
    __shared__ int sums[1024];
    int tid  = threadIdx.x;
    int base = tid * 4;
    int v0 = g_cnt[base + 0];
    int v1 = g_cnt[base + 1];
    int v2 = g_cnt[base + 2];
    int v3 = g_cnt[base + 3];
    int local = v0 + v1 + v2 + v3;
    sums[tid] = local;
    __syncthreads();
    for (int off = 1; off < 1024; off <<= 1) {
        int t = (tid >= off) ? sums[tid - off] : 0;
        __syncthreads();
        sums[tid] += t;
        __syncthreads();
    }
    int excl = sums[tid] - local;
    g_hh_ptr[base + 0] = excl;
    g_hh_ptr[base + 1] = excl + v0;
    g_hh_ptr[base + 2] = excl + v0 + v1;
    g_hh_ptr[base + 3] = excl + v0 + v1 + v2;
    if (tid == 1023) g_hh_ptr[H_DIM] = sums[1023];
    g_cnt[base + 0] = 0;
    g_cnt[base + 1] = 0;
    g_cnt[base + 2] = 0;
    g_cnt[base + 3] = 0;
}

// ---------------- hh scatter (int2) + ih densify ----------------
__global__ void k_build(const int* __restrict__ ih_rows, const int* __restrict__ ih_cols,
                        const float* __restrict__ ih_vals,
                        const int* __restrict__ hh_rows, const int* __restrict__ hh_cols,
                        const float* __restrict__ hh_vals) {
    int k = blockIdx.x * blockDim.x + threadIdx.x;
    if (k < NNZ_IH)
        atomicAdd(&g_W32[(size_t)ih_rows[k] * I_DIM + ih_cols[k]], ih_vals[k]);
    if (k < NNZ_HH) {
        int r = hh_rows[k];
        int p = g_hh_ptr[r] + atomicAdd(&g_cnt[r], 1);
        g_hh_pk[p] = make_int2(hh_cols[k], __float_as_int(hh_vals[k]));
    }
}

// ---------------- W32 -> W16 (R10-proven) ----------------
__global__ void k_cvt_w() {
    size_t idx = (size_t)blockIdx.x * blockDim.x + threadIdx.x;
    size_t n2  = (size_t)H_DIM * I_DIM / 2;
    if (idx < n2) {
        float2 v = ((const float2*)g_W32)[idx];
        ((__half2*)g_W16)[idx] = __floats2half2_rn(v.x, v.y);
    }
}

// ---------------- x (B,T,I) fp32 -> g_x16 (T,I,B) fp16 (R7-proven) ----------------
__global__ void k_transpose_x(const float* __restrict__ x) {
    __shared__ float tile[32][33];
    int t  = blockIdx.z;
    int i0 = blockIdx.x * 32;
    int b0 = blockIdx.y * 32;
    int b = b0 + threadIdx.y;
    int i = i0 + threadIdx.x;
    tile[threadIdx.y][threadIdx.x] = x[((size_t)b * T_STEPS + t) * I_DIM + i];
    __syncthreads();
    int iw = i0 + threadIdx.y;
    int bw = b0 + threadIdx.x;
    g_x16[((size_t)t * I_DIM + iw) * BATCH + bw] =
        __float2half(tile[threadIdx.x][threadIdx.y]);
}

// ---------------- pre GEMM: cp.async double-buffered wmma (R12-proven) ----------------
// C[4096, T*64] = W16[4096,1024] @ X[1024, T*64].
// Block tile 128x128 (128 rows x 2 timesteps), k-chunk 64 x 16 iters,
// 8 warps (4x2), warp tile 32x64 (2x4 wmma 16x16x16 frags, fp32 accum).
#define A_LD 72
#define B_LD 136
#define A_BYTES (128 * A_LD * 2)   // 18432
#define B_BYTES (64 * B_LD * 2)    // 17408
#define GEMM_SMEM (2 * (A_BYTES + B_BYTES))   // 71680

__global__ void __launch_bounds__(256)
k_gemm_pre() {
    extern __shared__ char smbase[];
    __half* Asm[2] = { (__half*)smbase, (__half*)(smbase + A_BYTES) };
    __half* Bsm[2] = { (__half*)(smbase + 2 * A_BYTES),
                       (__half*)(smbase + 2 * A_BYTES + B_BYTES) };
    float* fbuf = (float*)smbase;

    int tid  = threadIdx.x;
    int w    = tid >> 5;
    int lane = tid & 31;
    int wm   = w >> 1;
    int wn   = w & 1;
    int row0 = blockIdx.x * 128;
    int t0   = blockIdx.y * 2;

    const __half* __restrict__ Wp = g_W16 + (size_t)row0 * I_DIM;

    auto load_chunk = [&](int kc, int s) {
        const __half* asrc = Wp + kc * 64;
        #pragma unroll
        for (int p = 0; p < 4; p++) {
            int i   = tid + p * 256;
            int row = i >> 3;
            int seg = i & 7;
            cpa16(&Asm[s][row * A_LD + seg * 8],
                  asrc + (size_t)row * I_DIM + seg * 8);
        }
        #pragma unroll
        for (int p = 0; p < 4; p++) {
            int i    = tid + p * 256;
            int k    = i >> 4;
            int rest = i & 15;
            int tt   = rest >> 3;
            int seg  = rest & 7;
            cpa16(&Bsm[s][k * B_LD + tt * 64 + seg * 8],
                  g_x16 + (size_t)(t0 + tt) * I_DIM * BATCH
                        + (size_t)(kc * 64 + k) * BATCH + seg * 8);
        }
    };

    wmma::fragment<wmma::accumulator, 16, 16, 16, float> c[2][4];
    #pragma unroll
    for (int i = 0; i < 2; i++)
        #pragma unroll
        for (int j = 0; j < 4; j++)
            wmma::fill_fragment(c[i][j], 0.0f);

    load_chunk(0, 0);
    CPA_COMMIT();

    for (int kc = 0; kc < 16; kc++) {
        int s = kc & 1;
        if (kc < 15) {
            load_chunk(kc + 1, s ^ 1);
            CPA_COMMIT();
            CPA_WAIT(1);
        } else {
            CPA_WAIT(0);
        }
        __syncthreads();

        #pragma unroll
        for (int kk = 0; kk < 4; kk++) {
            wmma::fragment<wmma::matrix_a, 16, 16, 16, __half, wmma::row_major> a[2];
            wmma::fragment<wmma::matrix_b, 16, 16, 16, __half, wmma::row_major> b[4];
            wmma::load_matrix_sync(a[0], &Asm[s][(wm * 32) * A_LD + kk * 16], A_LD);
            wmma::load_matrix_sync(a[1], &Asm[s][(wm * 32 + 16) * A_LD + kk * 16], A_LD);
            #pragma unroll
            for (int j = 0; j < 4; j++)
                wmma::load_matrix_sync(b[j], &Bsm[s][(kk * 16) * B_LD + wn * 64 + j * 16], B_LD);
            #pragma unroll
            for (int i = 0; i < 2; i++)
                #pragma unroll
                for (int j = 0; j < 4; j++)
                    wmma::mma_sync(c[i][j], a[i], b[j], c[i][j]);
        }
        __syncthreads();
    }

    float* buf = fbuf + w * 2048;
    #pragma unroll
    for (int i = 0; i < 2; i++)
        #pragma unroll
        for (int j = 0; j < 4; j++)
            wmma::store_matrix_sync(buf + i * 16 * 64 + j * 16, c[i][j], 64,
                                    wmma::mem_row_major);
    __syncwarp();

    __half2* dst = (__half2*)(g_pre + (size_t)(t0 + wn) * H_DIM * BATCH);
    #pragma unroll
    for (int rr = 0; rr < 32; rr++) {
        float2 v = ((const float2*)(buf + rr * 64))[lane];
        dst[(size_t)(row0 + wm * 32 + rr) * (BATCH / 2) + lane] =
            __floats2half2_rn(v.x, v.y);
    }
}

// ---------------- per-timestep kernel (R10-proven: int2 weights, bias in step) ----------------
// block (32,16): each row served by a warp PAIR (k-split) -> 8192 warps chip-wide.
__global__ void __launch_bounds__(512)
k_step(const float* __restrict__ bias, float* __restrict__ out, int t, int prev) {
    int lane = threadIdx.x;
    int ty   = threadIdx.y;            // 0..15
    int ry   = ty & 7;
    int half = ty >> 3;
    int r    = blockIdx.x * ROWS_PER_BLK + ry;

    const __half2* __restrict__ hb = (const __half2*)g_h16[prev];

    int k0 = g_hh_ptr[r];
    int k1 = g_hh_ptr[r + 1];
    int mid = (k0 + k1 + 1) >> 1;
    int ka = half ? mid : k0;
    int kb = half ? k1  : mid;

    float ax = 0.0f, ay = 0.0f;
    #pragma unroll 4
    for (int k = ka; k < kb; k++) {
        int2 w = g_hh_pk[k];
        float v = __int_as_float(w.y);
        float2 f = __half22float2(hb[w.x * (BATCH / 2) + lane]);
        ax += v * f.x;
        ay += v * f.y;
    }

    __shared__ float2 part[ROWS_PER_BLK][32];
    __shared__ float  tile[ROWS_PER_BLK][BATCH + 1];

    if (half == 1) part[ry][lane] = make_float2(ax, ay);
    __syncthreads();

    if (half == 0) {
        float2 p = part[ry][lane];
        float bv = bias[r];
        float2 pre = __half22float2(
            ((const __half2*)(g_pre + (size_t)t * H_DIM * BATCH))
                [r * (BATCH / 2) + lane]);
        float hx = tanhf(bv + pre.x + ax + p.x);
        float hy = tanhf(bv + pre.y + ay + p.y);

        ((__half2*)g_h16[prev ^ 1])[r * (BATCH / 2) + lane] =
            __floats2half2_rn(hx, hy);

        tile[ry][2 * lane]     = hx;
        tile[ry][2 * lane + 1] = hy;
    }
    __syncthreads();

    // out (B,T,H) fp32, coalesced: 512 threads cover 512 elements
    int idx = ty * 32 + lane;
    int b   = idx >> 3;
    int rr  = idx & 7;
    out[((size_t)b * T_STEPS + t) * H_DIM + blockIdx.x * ROWS_PER_BLK + rr] =
        tile[rr][b];
}

// ---------------- launch ----------------
extern "C" void kernel_launch(void* const* d_in, const int* in_sizes, int n_in,
                              void* d_out, int out_size) {
    const float* x       = (const float*)d_in[0];
    const float* ih_vals = (const float*)d_in[1];
    const float* hh_vals = (const float*)d_in[2];
    const float* hh_bias = (const float*)d_in[3];
    const int*   ih_rows = (const int*)  d_in[4];
    const int*   ih_cols = (const int*)  d_in[5];
    const int*   hh_rows = (const int*)  d_in[6];
    const int*   hh_cols = (const int*)  d_in[7];
    float* out = (float*)d_out;

    static int smem_set = 0;
    if (!smem_set) {
        cudaFuncSetAttribute(k_gemm_pre, cudaFuncAttributeMaxDynamicSharedMemorySize,
                             GEMM_SMEM);
        smem_set = 1;
    }

    // ---- setup ----
    k_init<<<H_DIM * I_DIM / 4 / 256, 256>>>();
    k_hist<<<NNZ_HH / 256, 256>>>(hh_rows);
    k_scan<<<1, 1024>>>();
    k_build<<<NNZ_HH / 256, 256>>>(ih_rows, ih_cols, ih_vals,
                                   hh_rows, hh_cols, hh_vals);
    k_cvt_w<<<(H_DIM * I_DIM / 2 + 255) / 256, 256>>>();
    k_transpose_x<<<dim3(I_DIM / 32, BATCH / 32, T_STEPS), dim3(32, 32)>>>(x);

    // ---- ih term for all t via pipelined tensor-core GEMM ----
    k_gemm_pre<<<dim3(H_DIM / 128, T_STEPS / 2), 256, GEMM_SMEM>>>();

    // ---- sequential recurrence: hh gathers only ----
    for (int t = 0; t < T_STEPS; t++) {
        k_step<<<H_DIM / ROWS_PER_BLK, dim3(32, 16)>>>(hh_bias, out, t, t & 1);
    }
}

// round 16
// speedup vs baseline: 1.1059x; 1.0140x over previous
#include <cuda_runtime.h>
#include <cuda_fp16.h>
#include <math.h>

#define H_DIM   4096
#define BATCH   64
#define T_STEPS 128
#define I_DIM   1024
#define NNZ_IH  131072
#define NNZ_HH  262144

#define ROWS_PER_BLK 8      // preih row grouping (unchanged from R7)
#define STEP_RPB     4      // k_step rows per block (4-way k-split)

// ---------------- scratch (device globals; no runtime allocation) ----------------
__device__ __half g_x16[(size_t)T_STEPS * I_DIM * BATCH];   // x as (T, I, B) fp16
__device__ __half g_pre[(size_t)T_STEPS * H_DIM * BATCH];   // bias + W_ih x_t, fp16
__device__ __half g_h16[2][H_DIM * BATCH];                  // h ping-pong (H, B) fp16
__device__ int    g_ih_ptr[H_DIM + 1];
__device__ int    g_hh_ptr[H_DIM + 1];
__device__ int2   g_ih_pk[NNZ_IH];     // (col, val fp32 bits)
__device__ int2   g_hh_pk[NNZ_HH];
__device__ int    g_cnt[2 * H_DIM];

// ---------------- setup kernels (R7 verbatim) ----------------
__global__ void k_zero_all() {
    int idx = blockIdx.x * blockDim.x + threadIdx.x;
    if (idx < H_DIM * BATCH) g_h16[0][idx] = __float2half(0.0f);
    if (idx < 2 * H_DIM)     g_cnt[idx]   = 0;
}

__global__ void k_zero_cnt() {
    int idx = blockIdx.x * blockDim.x + threadIdx.x;
    if (idx < 2 * H_DIM) g_cnt[idx] = 0;
}

__global__ void k_hist(const int* __restrict__ ih_rows, const int* __restrict__ hh_rows) {
    int k = blockIdx.x * blockDim.x + threadIdx.x;
    if (k < NNZ_IH) atomicAdd(&g_cnt[ih_rows[k]], 1);
    if (k < NNZ_HH) atomicAdd(&g_cnt[H_DIM + hh_rows[k]], 1);
}

// exclusive scan of 4096 counts -> row pointers (one block per matrix)
__global__ void k_scan() {
    __shared__ int sums[1024];
    int which = blockIdx.x;              // 0 = ih, 1 = hh
    int* cnt = &g_cnt[which * H_DIM];
    int* ptr = which ? g_hh_ptr : g_ih_ptr;
    int tid  = threadIdx.x;
    int base = tid * 4;
    int v0 = cnt[base + 0];
    int v1 = cnt[base + 1];
    int v2 = cnt[base + 2];
    int v3 = cnt[base + 3];
    int local = v0 + v1 + v2 + v3;
    sums[tid] = local;
    __syncthreads();
    for (int off = 1; off < 1024; off <<= 1) {
        int t = (tid >= off) ? sums[tid - off] : 0;
        __syncthreads();
        sums[tid] += t;
        __syncthreads();
    }
    int excl = sums[tid] - local;
    ptr[base + 0] = excl;
    ptr[base + 1] = excl + v0;
    ptr[base + 2] = excl + v0 + v1;
    ptr[base + 3] = excl + v0 + v1 + v2;
    if (tid == 1023) ptr[H_DIM] = sums[1023];
}

__global__ void k_scatter(const int* __restrict__ ih_rows, const int* __restrict__ ih_cols,
                          const float* __restrict__ ih_vals,
                          const int* __restrict__ hh_rows, const int* __restrict__ hh_cols,
                          const float* __restrict__ hh_vals) {
    int k = blockIdx.x * blockDim.x + threadIdx.x;
    if (k < NNZ_IH) {
        int r = ih_rows[k];
        int p = g_ih_ptr[r] + atomicAdd(&g_cnt[r], 1);
        g_ih_pk[p] = make_int2(ih_cols[k], __float_as_int(ih_vals[k]));
    }
    if (k < NNZ_HH) {
        int r = hh_rows[k];
        int p = g_hh_ptr[r] + atomicAdd(&g_cnt[H_DIM + r], 1);
        g_hh_pk[p] = make_int2(hh_cols[k], __float_as_int(hh_vals[k]));
    }
}

// x (B,T,I) fp32 -> g_x16 (T,I,B) fp16
__global__ void k_transpose_x(const float* __restrict__ x) {
    __shared__ float tile[32][33];
    int t  = blockIdx.z;
    int i0 = blockIdx.x * 32;
    int b0 = blockIdx.y * 32;
    int b = b0 + threadIdx.y;
    int i = i0 + threadIdx.x;
    tile[threadIdx.y][threadIdx.x] = x[((size_t)b * T_STEPS + t) * I_DIM + i];
    __syncthreads();
    int iw = i0 + threadIdx.y;
    int bw = b0 + threadIdx.x;
    g_x16[((size_t)t * I_DIM + iw) * BATCH + bw] =
        __float2half(tile[threadIdx.x][threadIdx.y]);
}

// ---------------- ih precompute (R7 verbatim): pre[t] = bias + W_ih x_t ----------------
__global__ void __launch_bounds__(256)
k_preih(const float* __restrict__ bias) {
    int lane = threadIdx.x;
    int ty   = threadIdx.y;
    int r    = blockIdx.x * ROWS_PER_BLK + ty;
    int t    = blockIdx.y;

    const __half2* __restrict__ xb =
        (const __half2*)(g_x16 + (size_t)t * I_DIM * BATCH);

    float bv = bias[r];
    float ax = bv, ay = bv;

    int k0 = g_ih_ptr[r];
    int k1 = g_ih_ptr[r + 1];
    #pragma unroll 4
    for (int k = k0; k < k1; k++) {
        int2 w = g_ih_pk[k];
        float v = __int_as_float(w.y);
        float2 f = __half22float2(xb[w.x * (BATCH / 2) + lane]);
        ax += v * f.x;
        ay += v * f.y;
    }

    ((__half2*)(g_pre + (size_t)t * H_DIM * BATCH))[r * (BATCH / 2) + lane] =
        __floats2half2_rn(ax, ay);
}

// ---------------- per-timestep kernel: 4-way k-split per row ----------------
// block (32,16): 4 rows, each served by FOUR warps (quarter = ty>>2).
// 1024 blocks -> 16384 warps chip-wide: doubles in-flight gathers vs R7.
__global__ void __launch_bounds__(512)
k_step(float* __restrict__ out, int t, int prev) {
    int lane = threadIdx.x;
    int ty   = threadIdx.y;            // 0..15
    int ry   = ty & 3;                 // row within block (0..3)
    int q    = ty >> 2;                // quarter (0..3)
    int r    = blockIdx.x * STEP_RPB + ry;

    const __half2* __restrict__ hb = (const __half2*)g_h16[prev];

    int k0  = g_hh_ptr[r];
    int k1  = g_hh_ptr[r + 1];
    int len = k1 - k0;
    int ka  = k0 + (len * q) / 4;
    int kb  = k0 + (len * (q + 1)) / 4;

    float ax = 0.0f, ay = 0.0f;
    #pragma unroll 4
    for (int k = ka; k < kb; k++) {
        int2 w = g_hh_pk[k];
        float v = __int_as_float(w.y);
        float2 f = __half22float2(hb[w.x * (BATCH / 2) + lane]);
        ax += v * f.x;
        ay += v * f.y;
    }

    __shared__ float2 part[3][STEP_RPB][32];
    __shared__ float  tile[STEP_RPB][BATCH + 1];

    if (q > 0) part[q - 1][ry][lane] = make_float2(ax, ay);
    __syncthreads();

    if (q == 0) {
        float2 p1 = part[0][ry][lane];
        float2 p2 = part[1][ry][lane];
        float2 p3 = part[2][ry][lane];
        float2 pre = __half22float2(
            ((const __half2*)(g_pre + (size_t)t * H_DIM * BATCH))
                [r * (BATCH / 2) + lane]);
        float hx = tanhf(pre.x + ax + p1.x + p2.x + p3.x);
        float hy = tanhf(pre.y + ay + p1.y + p2.y + p3.y);

        // h(t) fp16: one 128B line per warp
        ((__half2*)g_h16[prev ^ 1])[r * (BATCH / 2) + lane] =
            __floats2half2_rn(hx, hy);

        tile[ry][2 * lane]     = hx;
        tile[ry][2 * lane + 1] = hy;
    }
    __syncthreads();

    // out (B,T,H) fp32, coalesced: 256 of 512 threads cover 4x64 elements
    int idx = ty * 32 + lane;                       // 0..511
    if (idx < STEP_RPB * BATCH) {
        int b  = idx >> 2;                          // 0..63
        int rr = idx & 3;                           // 0..3
        out[((size_t)b * T_STEPS + t) * H_DIM + blockIdx.x * STEP_RPB + rr] =
            tile[rr][b];
    }
}

// ---------------- launch ----------------
extern "C" void kernel_launch(void* const* d_in, const int* in_sizes, int n_in,
                              void* d_out, int out_size) {
    const float* x       = (const float*)d_in[0];
    const float* ih_vals = (const float*)d_in[1];
    const float* hh_vals = (const float*)d_in[2];
    const float* hh_bias = (const float*)d_in[3];
    const int*   ih_rows = (const int*)  d_in[4];
    const int*   ih_cols = (const int*)  d_in[5];
    const int*   hh_rows = (const int*)  d_in[6];
    const int*   hh_cols = (const int*)  d_in[7];
    float* out = (float*)d_out;

    // CSR build + x transpose/convert (R7 verbatim)
    k_zero_all<<<(H_DIM * BATCH + 255) / 256, 256>>>();
    k_hist<<<(NNZ_HH + 255) / 256, 256>>>(ih_rows, hh_rows);
    k_scan<<<2, 1024>>>();
    k_zero_cnt<<<(2 * H_DIM + 255) / 256, 256>>>();
    k_scatter<<<(NNZ_HH + 255) / 256, 256>>>(ih_rows, ih_cols, ih_vals,
                                             hh_rows, hh_cols, hh_vals);
    k_transpose_x<<<dim3(I_DIM / 32, BATCH / 32, T_STEPS), dim3(32, 32)>>>(x);

    // ih term for all timesteps at once
    k_preih<<<dim3(H_DIM / ROWS_PER_BLK, T_STEPS), dim3(32, ROWS_PER_BLK)>>>(hh_bias);

    // sequential recurrence: hh gathers only, 4-way k-split
    for (int t = 0; t < T_STEPS; t++) {
        k_step<<<H_DIM / STEP_RPB, dim3(32, 16)>>>(out, t, t & 1);
    }
}

// round 17
// speedup vs baseline: 1.2755x; 1.1533x over previous
#include <cuda_runtime.h>
#include <cuda_fp16.h>
#include <math.h>

#define H_DIM   4096
#define BATCH   64
#define T_STEPS 128
#define I_DIM   1024
#define NNZ_IH  131072
#define NNZ_HH  262144

#define ROWS_PER_BLK 8

// ---------------- scratch (device globals; no runtime allocation) ----------------
__device__ __half g_x16[(size_t)T_STEPS * I_DIM * BATCH];   // x as (T, I, B) fp16
__device__ __half g_pre[(size_t)T_STEPS * H_DIM * BATCH];   // bias + W_ih x_t, fp16
__device__ __half g_h16[2][H_DIM * BATCH];                  // h ping-pong (H, B) fp16
__device__ int    g_ih_ptr[H_DIM + 1];
__device__ int    g_hh_ptr[H_DIM + 1];
__device__ int2   g_ih_pk[NNZ_IH];     // (col, val fp32 bits)
__device__ int2   g_hh_pk[NNZ_HH];
__device__ int    g_cnt[2 * H_DIM];

// ---------------- setup kernels (R7 verbatim) ----------------
__global__ void k_zero_all() {
    int idx = blockIdx.x * blockDim.x + threadIdx.x;
    if (idx < H_DIM * BATCH) g_h16[0][idx] = __float2half(0.0f);
    if (idx < 2 * H_DIM)     g_cnt[idx]   = 0;
}

__global__ void k_zero_cnt() {
    int idx = blockIdx.x * blockDim.x + threadIdx.x;
    if (idx < 2 * H_DIM) g_cnt[idx] = 0;
}

__global__ void k_hist(const int* __restrict__ ih_rows, const int* __restrict__ hh_rows) {
    int k = blockIdx.x * blockDim.x + threadIdx.x;
    if (k < NNZ_IH) atomicAdd(&g_cnt[ih_rows[k]], 1);
    if (k < NNZ_HH) atomicAdd(&g_cnt[H_DIM + hh_rows[k]], 1);
}

// exclusive scan of 4096 counts -> row pointers (one block per matrix)
__global__ void k_scan() {
    __shared__ int sums[1024];
    int which = blockIdx.x;              // 0 = ih, 1 = hh
    int* cnt = &g_cnt[which * H_DIM];
    int* ptr = which ? g_hh_ptr : g_ih_ptr;
    int tid  = threadIdx.x;
    int base = tid * 4;
    int v0 = cnt[base + 0];
    int v1 = cnt[base + 1];
    int v2 = cnt[base + 2];
    int v3 = cnt[base + 3];
    int local = v0 + v1 + v2 + v3;
    sums[tid] = local;
    __syncthreads();
    for (int off = 1; off < 1024; off <<= 1) {
        int t = (tid >= off) ? sums[tid - off] : 0;
        __syncthreads();
        sums[tid] += t;
        __syncthreads();
    }
    int excl = sums[tid] - local;
    ptr[base + 0] = excl;
    ptr[base + 1] = excl + v0;
    ptr[base + 2] = excl + v0 + v1;
    ptr[base + 3] = excl + v0 + v1 + v2;
    if (tid == 1023) ptr[H_DIM] = sums[1023];
}

__global__ void k_scatter(const int* __restrict__ ih_rows, const int* __restrict__ ih_cols,
                          const float* __restrict__ ih_vals,
                          const int* __restrict__ hh_rows, const int* __restrict__ hh_cols,
                          const float* __restrict__ hh_vals) {
    int k = blockIdx.x * blockDim.x + threadIdx.x;
    if (k < NNZ_IH) {
        int r = ih_rows[k];
        int p = g_ih_ptr[r] + atomicAdd(&g_cnt[r], 1);
        g_ih_pk[p] = make_int2(ih_cols[k], __float_as_int(ih_vals[k]));
    }
    if (k < NNZ_HH) {
        int r = hh_rows[k];
        int p = g_hh_ptr[r] + atomicAdd(&g_cnt[H_DIM + r], 1);
        g_hh_pk[p] = make_int2(hh_cols[k], __float_as_int(hh_vals[k]));
    }
}

// x (B,T,I) fp32 -> g_x16 (T,I,B) fp16
__global__ void k_transpose_x(const float* __restrict__ x) {
    __shared__ float tile[32][33];
    int t  = blockIdx.z;
    int i0 = blockIdx.x * 32;
    int b0 = blockIdx.y * 32;
    int b = b0 + threadIdx.y;
    int i = i0 + threadIdx.x;
    tile[threadIdx.y][threadIdx.x] = x[((size_t)b * T_STEPS + t) * I_DIM + i];
    __syncthreads();
    int iw = i0 + threadIdx.y;
    int bw = b0 + threadIdx.x;
    g_x16[((size_t)t * I_DIM + iw) * BATCH + bw] =
        __float2half(tile[threadIdx.x][threadIdx.y]);
}

// ---------------- ih precompute (R7 verbatim): pre[t] = bias + W_ih x_t ----------------
__global__ void __launch_bounds__(256)
k_preih(const float* __restrict__ bias) {
    int lane = threadIdx.x;
    int ty   = threadIdx.y;
    int r    = blockIdx.x * ROWS_PER_BLK + ty;
    int t    = blockIdx.y;

    const __half2* __restrict__ xb =
        (const __half2*)(g_x16 + (size_t)t * I_DIM * BATCH);

    float bv = bias[r];
    float ax = bv, ay = bv;

    int k0 = g_ih_ptr[r];
    int k1 = g_ih_ptr[r + 1];
    #pragma unroll 4
    for (int k = k0; k < k1; k++) {
        int2 w = g_ih_pk[k];
        float v = __int_as_float(w.y);
        float2 f = __half22float2(xb[w.x * (BATCH / 2) + lane]);
        ax += v * f.x;
        ay += v * f.y;
    }

    ((__half2*)(g_pre + (size_t)t * H_DIM * BATCH))[r * (BATCH / 2) + lane] =
        __floats2half2_rn(ax, ay);
}

// ---------------- per-timestep kernel (R7 arithmetic + PDL restructure) ----------------
// block (32, 16): row handled by a warp PAIR (half = ty>>3).
// Prelude (before grid-dependency sync) touches only setup/preih data, which is
// complete: step 0 is a normal launch and PDL overlap depth is one kernel.
__global__ void __launch_bounds__(512)
k_step(float* __restrict__ out, int t, int prev) {
    int lane = threadIdx.x;
    int ty   = threadIdx.y;            // 0..15
    int ry   = ty & 7;
    int half = ty >> 3;
    int r    = blockIdx.x * ROWS_PER_BLK + ry;

    // ---- prelude: independent of h(t-1) ----
    int k0 = g_hh_ptr[r];
    int k1 = g_hh_ptr[r + 1];
    int mid = (k0 + k1 + 1) >> 1;
    int ka = half ? mid : k0;
    int kb = half ? k1  : mid;

    float2 pre = make_float2(0.f, 0.f);
    if (half == 0) {
        pre = __half22float2(
            ((const __half2*)(g_pre + (size_t)t * H_DIM * BATCH))
                [r * (BATCH / 2) + lane]);
    }
    // prefetch this segment's weight lines (contiguous, ~256B)
    if (lane < 4) {
        int kp = ka + lane * 16;
        if (kp < kb)
            asm volatile("prefetch.global.L1 [%0];" :: "l"(&g_hh_pk[kp]));
    }

    // ---- wait for h(t-1) from the preceding step kernel ----
#if __CUDA_ARCH__ >= 900
    cudaGridDependencySynchronize();
#endif

    const __half2* __restrict__ hb = (const __half2*)g_h16[prev];
    float ax = 0.0f, ay = 0.0f;
    #pragma unroll 4
    for (int k = ka; k < kb; k++) {
        int2 w = g_hh_pk[k];
        float v = __int_as_float(w.y);
        float2 f = __half22float2(hb[w.x * (BATCH / 2) + lane]);
        ax += v * f.x;
        ay += v * f.y;
    }

    __shared__ float2 part[ROWS_PER_BLK][32];
    __shared__ float  tile[ROWS_PER_BLK][BATCH + 1];

    if (half == 1) part[ry][lane] = make_float2(ax, ay);
    __syncthreads();

    if (half == 0) {
        float2 p = part[ry][lane];
        float hx = tanhf(pre.x + ax + p.x);
        float hy = tanhf(pre.y + ay + p.y);

        // h(t) fp16: one 128B line per warp
        ((__half2*)g_h16[prev ^ 1])[r * (BATCH / 2) + lane] =
            __floats2half2_rn(hx, hy);

        tile[ry][2 * lane]     = hx;
        tile[ry][2 * lane + 1] = hy;
    }
    __syncthreads();

    // ---- h(t) is written: release the next step before draining out-stores ----
#if __CUDA_ARCH__ >= 900
    cudaTriggerProgrammaticLaunchCompletion();
#endif

    // out (B,T,H) fp32, coalesced: 512 threads cover 512 elements
    int idx = ty * 32 + lane;                       // 0..511
    int b   = idx >> 3;                             // 0..63
    int rr  = idx & 7;                              // 0..7
    out[((size_t)b * T_STEPS + t) * H_DIM + blockIdx.x * ROWS_PER_BLK + rr] =
        tile[rr][b];
}

// ---------------- launch ----------------
extern "C" void kernel_launch(void* const* d_in, const int* in_sizes, int n_in,
                              void* d_out, int out_size) {
    const float* x       = (const float*)d_in[0];
    const float* ih_vals = (const float*)d_in[1];
    const float* hh_vals = (const float*)d_in[2];
    const float* hh_bias = (const float*)d_in[3];
    const int*   ih_rows = (const int*)  d_in[4];
    const int*   ih_cols = (const int*)  d_in[5];
    const int*   hh_rows = (const int*)  d_in[6];
    const int*   hh_cols = (const int*)  d_in[7];
    float* out = (float*)d_out;

    // CSR build + x transpose/convert (R7 verbatim)
    k_zero_all<<<(H_DIM * BATCH + 255) / 256, 256>>>();
    k_hist<<<(NNZ_HH + 255) / 256, 256>>>(ih_rows, hh_rows);
    k_scan<<<2, 1024>>>();
    k_zero_cnt<<<(2 * H_DIM + 255) / 256, 256>>>();
    k_scatter<<<(NNZ_HH + 255) / 256, 256>>>(ih_rows, ih_cols, ih_vals,
                                             hh_rows, hh_cols, hh_vals);
    k_transpose_x<<<dim3(I_DIM / 32, BATCH / 32, T_STEPS), dim3(32, 32)>>>(x);

    // ih term for all timesteps at once
    k_preih<<<dim3(H_DIM / ROWS_PER_BLK, T_STEPS), dim3(32, ROWS_PER_BLK)>>>(hh_bias);

    // step 0: normal launch (ensures preih/setup fully complete before PDL chain)
    k_step<<<H_DIM / ROWS_PER_BLK, dim3(32, 16)>>>(out, 0, 0);

    // steps 1..127: programmatic dependent launch — overlap each step's tail
    // (out-stores, teardown) with the next step's prelude and launch latency.
    cudaLaunchAttribute attr[1];
    attr[0].id = cudaLaunchAttributeProgrammaticStreamSerialization;
    attr[0].val.programmaticStreamSerializationAllowed = 1;

    cudaLaunchConfig_t cfg = {};
    cfg.gridDim  = dim3(H_DIM / ROWS_PER_BLK, 1, 1);
    cfg.blockDim = dim3(32, 16, 1);
    cfg.dynamicSmemBytes = 0;
    cfg.stream = 0;
    cfg.attrs = attr;
    cfg.numAttrs = 1;

    for (int t = 1; t < T_STEPS; t++) {
        cudaLaunchKernelEx(&cfg, k_step, out, t, t & 1);
    }
}